// round 1
// baseline (speedup 1.0000x reference)
#include <cuda_runtime.h>
#include <cuda_bf16.h>
#include <cstdint>

// VQ-VAE nearest-codebook quantization.
// Inputs:  d_in[0] = z          (D=1024, 64, 64) fp32  -> viewed as (D, N=4096), tokens are columns
//          d_in[1] = code_books (D=1024, 64, 64) fp32  -> viewed as (D, K=4096), codes are columns
// Output:  d_out = concat(z_st, zq), each (D, 64, 64) fp32 -> (D, N)
//   idx[n] = argmin_k ( ||cb_k||^2 - 2 * z_n . cb_k )   (||z_n||^2 constant per n, dropped)
//   zq[:,n] = cb[:, idx[n]];  z_st = zq + (z - zq)
//
// Precision: argmin gaps are ~O(6) in d2 units but can be small for some tokens;
// fp32 accumulation keeps dot error ~1e-5, far below any plausible gap.

#define NTOK 4096   // N = K = 64*64

__device__ unsigned long long g_best[NTOK];   // packed (ordered_d2 << 32) | k
__device__ float g_cbnorm[NTOK];

// ---------------------------------------------------------------------------
// Kernel A: cbnorm[k] = sum_d cb[d,k]^2 ; init g_best.
// 128 blocks x 256 threads; 8 row-slices per column, coalesced across k.
// ---------------------------------------------------------------------------
__global__ void vq_prep_kernel(const float* __restrict__ CB, int D) {
    __shared__ float red[256];
    const int c = threadIdx.x & 31;
    const int h = threadIdx.x >> 5;            // 0..7
    const int k = blockIdx.x * 32 + c;
    float s = 0.f;
    for (int d = h; d < D; d += 8) {
        float v = CB[(size_t)d * NTOK + k];
        s += v * v;
    }
    red[threadIdx.x] = s;
    __syncthreads();
    if (h == 0) {
        float t = 0.f;
        #pragma unroll
        for (int i = 0; i < 8; i++) t += red[i * 32 + c];
        g_cbnorm[k] = t;
    }
    if (h == 1) g_best[k] = 0xFFFFFFFFFFFFFFFFull;
}

// ---------------------------------------------------------------------------
// Kernel B: fused fp32 GEMM (S = Z^T * CB over D) + argmin over k.
// Tile: BM=128 (n) x BN=128 (k) x BK=16 (d). 256 threads, 8x8 register tiles.
// Epilogue: per-thread argmin over its 8 k's, shfl-reduce over the 16 threads
// sharing each n-row, then one atomicMin per n-row into g_best.
// ---------------------------------------------------------------------------
#define BM 128
#define BN 128
#define BK 16
#define TM 8
#define TN 8

__device__ __forceinline__ unsigned order_f32(float f) {
    unsigned u = __float_as_uint(f);
    return (u & 0x80000000u) ? ~u : (u | 0x80000000u);
}

__global__ __launch_bounds__(256, 2)
void vq_dist_argmin_kernel(const float* __restrict__ Z, const float* __restrict__ CB, int D) {
    __shared__ float As[BK][BM];
    __shared__ float Bs[BK][BN];

    const int n0 = blockIdx.x * BM;
    const int k0 = blockIdx.y * BN;
    const int tid = threadIdx.x;
    const int tx = tid & 15;    // k group (16 groups x 8 = 128)
    const int ty = tid >> 4;    // n group

    float acc[TM][TN];
    #pragma unroll
    for (int i = 0; i < TM; i++)
        #pragma unroll
        for (int j = 0; j < TN; j++) acc[i][j] = 0.f;

    for (int d0 = 0; d0 < D; d0 += BK) {
        // Load 16x128 tiles of Z and CB (rows contiguous in n/k -> float4, coalesced).
        #pragma unroll
        for (int v = 0; v < 2; v++) {
            int e  = tid + v * 256;        // 512 float4 per tile
            int r  = e >> 5;               // 32 float4 per row
            int c4 = (e & 31) << 2;
            *reinterpret_cast<float4*>(&As[r][c4]) =
                *reinterpret_cast<const float4*>(&Z[(size_t)(d0 + r) * NTOK + n0 + c4]);
            *reinterpret_cast<float4*>(&Bs[r][c4]) =
                *reinterpret_cast<const float4*>(&CB[(size_t)(d0 + r) * NTOK + k0 + c4]);
        }
        __syncthreads();

        #pragma unroll
        for (int d = 0; d < BK; d++) {
            float a[TM], b[TN];
            #pragma unroll
            for (int i = 0; i < TM; i++) a[i] = As[d][ty * TM + i];
            #pragma unroll
            for (int j = 0; j < TN; j++) b[j] = Bs[d][tx * TN + j];
            #pragma unroll
            for (int i = 0; i < TM; i++)
                #pragma unroll
                for (int j = 0; j < TN; j++)
                    acc[i][j] += a[i] * b[j];
        }
        __syncthreads();
    }

    // Epilogue: d2 = cbnorm[k] - 2*dot ; argmin over this block's 128 k's.
    float cbn[TN];
    #pragma unroll
    for (int j = 0; j < TN; j++) cbn[j] = g_cbnorm[k0 + tx * TN + j];

    unsigned long long pk[TM];
    #pragma unroll
    for (int i = 0; i < TM; i++) {
        float best_d = __int_as_float(0x7F800000);  // +inf
        int   best_k = k0 + tx * TN;
        #pragma unroll
        for (int j = 0; j < TN; j++) {
            float d2 = fmaf(-2.f, acc[i][j], cbn[j]);
            if (d2 < best_d) { best_d = d2; best_k = k0 + tx * TN + j; }
        }
        pk[i] = ((unsigned long long)order_f32(best_d) << 32) | (unsigned)best_k;
    }

    // Reduce over the 16 tx-threads sharing each n-row (lanes 0..15 / 16..31 per warp).
    #pragma unroll
    for (int i = 0; i < TM; i++) {
        #pragma unroll
        for (int off = 1; off < 16; off <<= 1) {
            unsigned long long o = __shfl_xor_sync(0xFFFFFFFFu, pk[i], off);
            if (o < pk[i]) pk[i] = o;
        }
    }
    if (tx == 0) {
        #pragma unroll
        for (int i = 0; i < TM; i++)
            atomicMin(&g_best[n0 + ty * TM + i], pk[i]);
    }
}

// ---------------------------------------------------------------------------
// Kernel C: gather zq = cb[:, idx[n]] and write [z_st, zq].
// grid (N/256, D/16); z reads & all writes coalesced; cb gather hits L2.
// ---------------------------------------------------------------------------
__global__ void vq_gather_kernel(const float* __restrict__ Z, const float* __restrict__ CB,
                                 float* __restrict__ out, int D, int writeQ) {
    const int n = blockIdx.x * 256 + threadIdx.x;
    const unsigned k = (unsigned)(g_best[n] & 0xFFFFFFFFu);
    const int d0 = blockIdx.y * 16;
    float* out_q = out + (size_t)D * NTOK;
    #pragma unroll
    for (int d = d0; d < d0 + 16; d++) {
        float q = CB[(size_t)d * NTOK + k];
        float z = Z[(size_t)d * NTOK + n];
        out[(size_t)d * NTOK + n] = q + (z - q);   // straight-through value
        if (writeQ) out_q[(size_t)d * NTOK + n] = q;
    }
}

// ---------------------------------------------------------------------------
extern "C" void kernel_launch(void* const* d_in, const int* in_sizes, int n_in,
                              void* d_out, int out_size) {
    const float* Z  = (const float*)d_in[0];
    const float* CB = (const float*)d_in[1];
    float* out = (float*)d_out;
    const int D = in_sizes[0] / NTOK;               // 1024
    const int writeQ = (out_size >= 2 * D * NTOK) ? 1 : 0;

    vq_prep_kernel<<<NTOK / 32, 256>>>(CB, D);
    dim3 gridB(NTOK / BM, NTOK / BN);
    vq_dist_argmin_kernel<<<gridB, 256>>>(Z, CB, D);
    dim3 gridC(NTOK / 256, D / 16);
    vq_gather_kernel<<<gridC, 256>>>(Z, CB, out, D, writeQ);
}

// round 3
// speedup vs baseline: 3.8538x; 3.8538x over previous
#include <cuda_runtime.h>
#include <cuda_bf16.h>
#include <cstdint>

// VQ-VAE nearest-codebook quantization.
//   idx[n] = argmin_k (||cb_k||^2 - 2 z_n . cb_k);  zq = cb[idx];  z_st = zq + (z - zq)
// Coarse pass: bf16 mma.sync (HMMA) GEMM -> coarse d2 (error << MARGIN).
// Rescue: all k with coarse d2 < coarse_min + MARGIN get an exact fp32 rescore.
// NOTE: tcgen05 is unavailable (ptxas target is base sm_100) — use mma.sync.

#define NTOK 4096
#define DDIM 1024
#define CAP_CAND (1 << 18)
#define MARGIN 2.0f

// ---- device scratch (no allocations allowed) ----
__device__ unsigned long long g_final[NTOK];               // exact packed (ord(d2)<<32)|k
__device__ float g_cbnorm[NTOK];
__device__ float g_nrm_part[16][NTOK];                     // per-d-chunk partial norms
__device__ float g_Zt[(size_t)NTOK * DDIM];                // fp32 token-major (rescore)
__device__ float g_CBt[(size_t)NTOK * DDIM];
__device__ __align__(16) __nv_bfloat16 g_Zh[(size_t)NTOK * DDIM];   // bf16 row-major
__device__ __align__(16) __nv_bfloat16 g_CBh[(size_t)NTOK * DDIM];
__device__ float g_d2[(size_t)NTOK * NTOK];                // coarse d2 [token][code]
__device__ unsigned g_cand[CAP_CAND];
__device__ unsigned g_ncand;

// ---- helpers ----
__device__ __forceinline__ uint32_t smem_u32(const void* p) {
    uint32_t a;
    asm("{ .reg .u64 t; cvta.to.shared.u64 t, %1; cvt.u32.u64 %0, t; }" : "=r"(a) : "l"(p));
    return a;
}
__device__ __forceinline__ unsigned order_f32(float f) {
    unsigned u = __float_as_uint(f);
    return (u & 0x80000000u) ? ~u : (u | 0x80000000u);
}
__device__ __forceinline__ float unorder_f32(unsigned u) {
    return (u & 0x80000000u) ? __uint_as_float(u ^ 0x80000000u) : __uint_as_float(~u);
}
__device__ __forceinline__ void cp_async16(uint32_t dst, const void* src) {
    asm volatile("cp.async.cg.shared.global [%0], [%1], 16;" :: "r"(dst), "l"(src));
}
__device__ __forceinline__ void cp_commit() { asm volatile("cp.async.commit_group;"); }
__device__ __forceinline__ void cp_wait1()  { asm volatile("cp.async.wait_group 1;"); }
__device__ __forceinline__ void ldsm4(uint32_t (&r)[4], uint32_t addr) {
    asm volatile("ldmatrix.sync.aligned.m8n8.x4.shared.b16 {%0,%1,%2,%3}, [%4];"
                 : "=r"(r[0]), "=r"(r[1]), "=r"(r[2]), "=r"(r[3]) : "r"(addr));
}
__device__ __forceinline__ void mma16816(float (&c)[4], const uint32_t (&a)[4],
                                         uint32_t b0, uint32_t b1) {
    asm volatile(
        "mma.sync.aligned.m16n8k16.row.col.f32.bf16.bf16.f32 "
        "{%0,%1,%2,%3}, {%4,%5,%6,%7}, {%8,%9}, {%0,%1,%2,%3};"
        : "+f"(c[0]), "+f"(c[1]), "+f"(c[2]), "+f"(c[3])
        : "r"(a[0]), "r"(a[1]), "r"(a[2]), "r"(a[3]), "r"(b0), "r"(b1));
}
// Swizzled smem tile address: 128 rows x 4 k-granules (16B each).
// Layout packs 2 rows per 128B line; xor over ((row>>1)&7) makes both the
// cp.async stores and every ldmatrix 8-lane phase hit 8 distinct 16B groups.
__device__ __forceinline__ uint32_t sw_addr(uint32_t base, int row, int kg) {
    return base + ((row >> 1) << 7) + ((((kg + ((row & 1) << 2)) ^ ((row >> 1) & 7))) << 4);
}

// ---------------------------------------------------------------------------
// init
// ---------------------------------------------------------------------------
__global__ void vq_init() {
    int i = blockIdx.x * 256 + threadIdx.x;
    if (i < NTOK) g_final[i] = ~0ull;
    if (i == 0) g_ncand = 0;
}

// ---------------------------------------------------------------------------
// prep: transpose to token-major fp32 + bf16 row-major + partial cb norms
// grid (32 nb, 16 dc, 2 which), 256 threads. Block = 128 cols x 64 dims.
// ---------------------------------------------------------------------------
__global__ void vq_prep(const float* __restrict__ Z, const float* __restrict__ CB) {
    __shared__ float tile[64 * 129];
    const int nb = blockIdx.x, dc = blockIdx.y, which = blockIdx.z;
    const float* src = which ? CB : Z;
    float* dstT = which ? g_CBt : g_Zt;
    __nv_bfloat16* dstH = which ? g_CBh : g_Zh;
    const int tid = threadIdx.x;

    for (int idx = tid; idx < 64 * 128; idx += 256) {
        int d = idx >> 7, n = idx & 127;
        tile[d * 129 + n] = src[(size_t)(dc * 64 + d) * NTOK + nb * 128 + n];
    }
    __syncthreads();
    // fp32 token-major (coalesced over d)
    for (int idx = tid; idx < 64 * 128; idx += 256) {
        int n = idx >> 6, d = idx & 63;
        dstT[(size_t)(nb * 128 + n) * DDIM + dc * 64 + d] = tile[d * 129 + n];
    }
    // bf16 row-major (token, dim), written as bf16x2 pairs
    for (int idx = tid; idx < 64 * 64; idx += 256) {
        int n = idx >> 5, dd = (idx & 31) << 1;
        __nv_bfloat162 h2 = __floats2bfloat162_rn(tile[dd * 129 + n], tile[(dd + 1) * 129 + n]);
        *reinterpret_cast<__nv_bfloat162*>(
            &dstH[(size_t)(nb * 128 + n) * DDIM + dc * 64 + dd]) = h2;
    }
    // exact partial norms, fixed order (deterministic)
    if (which && tid < 128) {
        float s = 0.f;
        #pragma unroll 8
        for (int d = 0; d < 64; d++) { float v = tile[d * 129 + tid]; s += v * v; }
        g_nrm_part[dc][nb * 128 + tid] = s;
    }
}

__global__ void vq_norm_combine() {
    int k = blockIdx.x * 256 + threadIdx.x;
    float s = 0.f;
    #pragma unroll
    for (int i = 0; i < 16; i++) s += g_nrm_part[i][k];
    g_cbnorm[k] = s;
}

// ---------------------------------------------------------------------------
// coarse GEMM: bf16 mma.sync m16n8k16, tile 128 tokens x 128 codes x 32 dims,
// 3-stage cp.async pipeline. 256 threads = 8 warps (2 in M x 4 in N),
// warp tile 64x32. Epilogue: d2 = cbnorm - 2*dot -> g_d2[t][k].
// ---------------------------------------------------------------------------
#define STG_B 16384     // A 8KB + B 8KB per stage

__global__ __launch_bounds__(256, 2) void vq_gemm() {
    __shared__ __align__(1024) char sm[3 * STG_B];
    const uint32_t smb = smem_u32(sm);
    const int tid = threadIdx.x, wid = tid >> 5, lane = tid & 31;
    const int warp_m = wid & 1, warp_n = wid >> 1;
    const int t0 = blockIdx.x * 128, k0 = blockIdx.y * 128;
    const char* zp = (const char*)g_Zh + (size_t)t0 * DDIM * 2;
    const char* cp = (const char*)g_CBh + (size_t)k0 * DDIM * 2;

    float acc[4][4][4];
    #pragma unroll
    for (int i = 0; i < 4; i++)
        #pragma unroll
        for (int j = 0; j < 4; j++)
            #pragma unroll
            for (int q = 0; q < 4; q++) acc[i][j][q] = 0.f;

    // stage loader: 1024 granules of 16B (A rows 0..127, then B rows 0..127)
    auto load_stage = [&](int stg, int kc) {
        const uint32_t sbase = smb + stg * STG_B;
        #pragma unroll
        for (int u = 0; u < 4; u++) {
            int i = tid + u * 256;
            int r = (i >> 2) & 127;
            int c = i & 3;
            bool isB = i >= 512;
            uint32_t dst = sw_addr(sbase + (isB ? 8192 : 0), r, c);
            const char* src = (isB ? cp + (size_t)r * 2048 : zp + (size_t)r * 2048)
                              + kc * 64 + c * 16;
            cp_async16(dst, src);
        }
        cp_commit();
    };

    load_stage(0, 0);
    load_stage(1, 1);

    for (int kc = 0; kc < 32; kc++) {
        cp_wait1();
        __syncthreads();
        if (kc + 2 < 32) load_stage((kc + 2) % 3, kc + 2);

        const uint32_t sA = smb + (kc % 3) * STG_B;
        const uint32_t sB = sA + 8192;
        #pragma unroll
        for (int s = 0; s < 2; s++) {
            uint32_t a[4][4], b[2][4];
            #pragma unroll
            for (int mt = 0; mt < 4; mt++) {
                int row = warp_m * 64 + mt * 16 + ((lane >> 3) & 1) * 8 + (lane & 7);
                int kg = s * 2 + (lane >> 4);
                ldsm4(a[mt], sw_addr(sA, row, kg));
            }
            #pragma unroll
            for (int np = 0; np < 2; np++) {
                int row = warp_n * 32 + np * 16 + ((lane >> 4) << 3) + (lane & 7);
                int kg = s * 2 + ((lane >> 3) & 1);
                ldsm4(b[np], sw_addr(sB, row, kg));
            }
            #pragma unroll
            for (int mt = 0; mt < 4; mt++) {
                #pragma unroll
                for (int np = 0; np < 2; np++) {
                    mma16816(acc[mt][np * 2 + 0], a[mt], b[np][0], b[np][1]);
                    mma16816(acc[mt][np * 2 + 1], a[mt], b[np][2], b[np][3]);
                }
            }
        }
        __syncthreads();
    }

    // epilogue: d2 = cbnorm[k] - 2*dot -> g_d2[t][k]
    const int kbase = k0 + warp_n * 32 + (lane & 3) * 2;
    float2 cbn[4];
    #pragma unroll
    for (int nt = 0; nt < 4; nt++)
        cbn[nt] = *reinterpret_cast<const float2*>(&g_cbnorm[kbase + nt * 8]);

    #pragma unroll
    for (int mt = 0; mt < 4; mt++) {
        #pragma unroll
        for (int half = 0; half < 2; half++) {
            int t = t0 + warp_m * 64 + mt * 16 + (lane >> 2) + half * 8;
            float* row = g_d2 + (size_t)t * NTOK;
            #pragma unroll
            for (int nt = 0; nt < 4; nt++) {
                float2 v;
                v.x = fmaf(-2.f, acc[mt][nt][half * 2 + 0], cbn[nt].x);
                v.y = fmaf(-2.f, acc[mt][nt][half * 2 + 1], cbn[nt].y);
                *reinterpret_cast<float2*>(&row[kbase + nt * 8]) = v;
            }
        }
    }
}

// ---------------------------------------------------------------------------
// scan: warp per token; pass 1 = min over coarse d2, pass 2 = collect
// candidates with d2 < min + MARGIN.
// ---------------------------------------------------------------------------
__global__ void vq_scan() {
    const int w = threadIdx.x >> 5, lane = threadIdx.x & 31;
    const int t = blockIdx.x * 8 + w;
    const float* row = g_d2 + (size_t)t * NTOK;
    unsigned long long best = ~0ull;
    for (int j = lane; j < NTOK; j += 32) {
        unsigned long long pk = ((unsigned long long)order_f32(row[j]) << 32) | (unsigned)j;
        if (pk < best) best = pk;
    }
    #pragma unroll
    for (int o = 16; o; o >>= 1) {
        unsigned long long v = __shfl_xor_sync(0xFFFFFFFFu, best, o);
        if (v < best) best = v;
    }
    const float thr = unorder_f32((unsigned)(best >> 32)) + MARGIN;
    for (int j = lane; j < NTOK; j += 32) {
        if (row[j] < thr) {
            unsigned pos = atomicAdd(&g_ncand, 1u);
            if (pos < CAP_CAND) g_cand[pos] = ((unsigned)t << 12) | (unsigned)j;
        }
    }
}

// ---------------------------------------------------------------------------
// rescore: exact fp32 dot per candidate (one warp each) -> g_final
// ---------------------------------------------------------------------------
__global__ void vq_rescore() {
    const int wg = blockIdx.x * 4 + (threadIdx.x >> 5);
    const int lane = threadIdx.x & 31;
    unsigned cnt = g_ncand; if (cnt > CAP_CAND) cnt = CAP_CAND;
    for (unsigned c = wg; c < cnt; c += gridDim.x * 4) {
        unsigned e = g_cand[c];
        int n = e >> 12, k = e & 4095;
        const float4* za = (const float4*)(g_Zt  + (size_t)n * DDIM);
        const float4* cb = (const float4*)(g_CBt + (size_t)k * DDIM);
        float s = 0.f;
        #pragma unroll
        for (int j = 0; j < 8; j++) {
            float4 a = za[j * 32 + lane], b = cb[j * 32 + lane];
            s = fmaf(a.x, b.x, s); s = fmaf(a.y, b.y, s);
            s = fmaf(a.z, b.z, s); s = fmaf(a.w, b.w, s);
        }
        #pragma unroll
        for (int o = 16; o; o >>= 1) s += __shfl_xor_sync(0xFFFFFFFFu, s, o);
        if (lane == 0) {
            float d2 = fmaf(-2.f, s, g_cbnorm[k]);
            unsigned long long pk = ((unsigned long long)order_f32(d2) << 32) | (unsigned)k;
            atomicMin(&g_final[n], pk);
        }
    }
}

// ---------------------------------------------------------------------------
// gather: zq = cb[:, idx]; out = [z_st, zq]
// ---------------------------------------------------------------------------
__global__ void vq_gather(const float* __restrict__ Z, const float* __restrict__ CB,
                          float* __restrict__ out, int writeQ) {
    const int n = blockIdx.x * 256 + threadIdx.x;
    const unsigned k = (unsigned)(g_final[n] & 0xFFFFFFFFu);
    const int d0 = blockIdx.y * 16;
    float* out_q = out + (size_t)DDIM * NTOK;
    #pragma unroll
    for (int d = d0; d < d0 + 16; d++) {
        float q = CB[(size_t)d * NTOK + k];
        float z = Z[(size_t)d * NTOK + n];
        out[(size_t)d * NTOK + n] = q + (z - q);
        if (writeQ) out_q[(size_t)d * NTOK + n] = q;
    }
}

// ---------------------------------------------------------------------------
extern "C" void kernel_launch(void* const* d_in, const int* in_sizes, int n_in,
                              void* d_out, int out_size) {
    const float* Z  = (const float*)d_in[0];
    const float* CB = (const float*)d_in[1];
    float* out = (float*)d_out;
    const int writeQ = (out_size >= 2 * DDIM * NTOK) ? 1 : 0;

    vq_init<<<16, 256>>>();
    vq_prep<<<dim3(32, 16, 2), 256>>>(Z, CB);
    vq_norm_combine<<<16, 256>>>();
    vq_gemm<<<dim3(32, 32), 256>>>();
    vq_scan<<<512, 256>>>();
    vq_rescore<<<512, 128>>>();
    vq_gather<<<dim3(16, 64), 256>>>(Z, CB, out, writeQ);
}